// round 4
// baseline (speedup 1.0000x reference)
#include <cuda_runtime.h>

// MedSegNet texture features, algebraically folded (theta=1):
//   g        = cl*ln(cl), cl = max(p,1e-6)  (precomputed once per input cell)
//   box sums of p, p^2, g via per-thread column sums; ssq = P2 - S*mean
//   contrast*e^-.5 = min(max(ssq*67392.295, 1e-4), 8/9*e^-.5)
//   M(f)     = fmaxf(f * exp(-0.5), 1e-4)
// Round 4: 2x4 output block per thread (adjacent rows) -> 33% fewer LDS
// wavefronts, shared s12 partials for the two vertically-overlapping windows.

#define H 128
#define W 128
#define NPLANES 512        // B*C = 8*64
#define TILE_H 16
#define SH (TILE_H + 2)
#define SW2 132            // padded row stride (16B-aligned rows)
#define GPAD (-1.3815511e-5f)   // 1e-6 * ln(1e-6)

__global__ __launch_bounds__(256, 4)
void medseg_kernel(const float* __restrict__ x, float* __restrict__ out) {
    const int bc = blockIdx.y;
    const int rowBase = blockIdx.x * TILE_H;

    __shared__ __align__(16) float sp[SH][SW2];
    __shared__ __align__(16) float sg[SH][SW2];

    const int tx = threadIdx.x;                // 0..31
    const int ty = threadIdx.y;                // 0..7

    const float* __restrict__ plane = x + (size_t)bc * (H * W);

    // ---- load phase: warp ty fills shared rows ty, ty+8, ty+16 ----
    #pragma unroll
    for (int rep = 0; rep < 3; rep++) {
        const int sr = ty + rep * 8;
        if (sr < SH) {
            const int gr = rowBase + sr - 1;
            if ((unsigned)gr < (unsigned)H) {
                const float* __restrict__ rp = plane + gr * W;
                #pragma unroll
                for (int k = 0; k < 4; k++) {
                    const float p = rp[tx + 32 * k];
                    const float cl = fmaxf(p, 1e-6f);
                    sp[sr][tx + 32 * k + 1] = p;
                    sg[sr][tx + 32 * k + 1] = cl * __logf(cl);
                }
            } else {
                #pragma unroll
                for (int k = 0; k < 4; k++) {
                    sp[sr][tx + 32 * k + 1] = 0.0f;
                    sg[sr][tx + 32 * k + 1] = GPAD;
                }
            }
            if (tx == 0) {
                sp[sr][0]   = 0.0f;  sg[sr][0]   = GPAD;
                sp[sr][129] = 0.0f;  sg[sr][129] = GPAD;
            }
        }
    }
    __syncthreads();

    const float INV9 = 1.0f / 9.0f;
    const float EMH  = 0.60653066f;            // exp(-0.5)
    const float C89E = 0.53913838f;            // (8/9)*exp(-0.5)
    const float CCLP = 67392.295f;             // (1e6/9)*exp(-0.5)
    const float CE9  = 0.067392295f;           // exp(-0.5)/9

    float* __restrict__ outp = out + (size_t)(4 * bc) * (H * W);

    // Thread computes output rows 2ty (window A) and 2ty+1 (window B),
    // cols 4tx..4tx+3. Windows span shared rows [2ty..2ty+2] and [2ty+1..2ty+3].
    const int sr0 = 2 * ty;                    // topmost shared row of the 4-row block
    const int sc  = 4 * tx;                    // shared col of (global col 4tx - 1)

    // 4x6 register block of p (aligned LDS.128 + LDS.64)
    float p[4][6];
    #pragma unroll
    for (int r = 0; r < 4; r++) {
        const float4 a = *(const float4*)&sp[sr0 + r][sc];
        const float2 b = *(const float2*)&sp[sr0 + r][sc + 4];
        p[r][0]=a.x; p[r][1]=a.y; p[r][2]=a.z; p[r][3]=a.w; p[r][4]=b.x; p[r][5]=b.y;
    }

    // g column sums: rows consumed immediately (never all live)
    float cgA[6], cgB[6];
    {
        float t1[6], t2[6];
        { const float4 a = *(const float4*)&sg[sr0 + 1][sc];
          const float2 b = *(const float2*)&sg[sr0 + 1][sc + 4];
          t1[0]=a.x; t1[1]=a.y; t1[2]=a.z; t1[3]=a.w; t1[4]=b.x; t1[5]=b.y; }
        { const float4 a = *(const float4*)&sg[sr0 + 2][sc];
          const float2 b = *(const float2*)&sg[sr0 + 2][sc + 4];
          t2[0]=a.x; t2[1]=a.y; t2[2]=a.z; t2[3]=a.w; t2[4]=b.x; t2[5]=b.y; }
        #pragma unroll
        for (int j = 0; j < 6; j++) t1[j] += t2[j];          // s12g
        { const float4 a = *(const float4*)&sg[sr0][sc];
          const float2 b = *(const float2*)&sg[sr0][sc + 4];
          t2[0]=a.x; t2[1]=a.y; t2[2]=a.z; t2[3]=a.w; t2[4]=b.x; t2[5]=b.y; }
        #pragma unroll
        for (int j = 0; j < 6; j++) cgA[j] = t1[j] + t2[j];
        { const float4 a = *(const float4*)&sg[sr0 + 3][sc];
          const float2 b = *(const float2*)&sg[sr0 + 3][sc + 4];
          t2[0]=a.x; t2[1]=a.y; t2[2]=a.z; t2[3]=a.w; t2[4]=b.x; t2[5]=b.y; }
        #pragma unroll
        for (int j = 0; j < 6; j++) cgB[j] = t1[j] + t2[j];
    }

    // p / p^2 column sums via shared middle partials
    float cpA[6], cpB[6], cqA[6], cqB[6];
    #pragma unroll
    for (int j = 0; j < 6; j++) {
        const float s12p = p[1][j] + p[2][j];
        cpA[j] = s12p + p[0][j];
        cpB[j] = s12p + p[3][j];
        const float s12q = fmaf(p[1][j], p[1][j], p[2][j] * p[2][j]);
        cqA[j] = fmaf(p[0][j], p[0][j], s12q);
        cqB[j] = fmaf(p[3][j], p[3][j], s12q);
    }

    float* opA = outp + (rowBase + 2 * ty) * W + 4 * tx;

    // ---- window A (rows sr0..sr0+2) ----
    {
        float m0v[4], m1v[4], m2v[4], m3v[4];
        #pragma unroll
        for (int i = 0; i < 4; i++) {
            const float S  = cpA[i] + cpA[i+1] + cpA[i+2];
            const float P2 = cqA[i] + cqA[i+1] + cqA[i+2];
            const float G  = cgA[i] + cgA[i+1] + cgA[i+2];
            const float mean = S * INV9;
            const float ssq  = fmaf(-S, mean, P2);
            float sab = 0.0f;
            #pragma unroll
            for (int r = 0; r < 3; r++) {
                sab += fabsf(p[r][i]     - mean);
                sab += fabsf(p[r][i + 1] - mean);
                sab += fabsf(p[r][i + 2] - mean);
            }
            m0v[i] = fminf(fmaxf(ssq * CCLP, 1e-4f), C89E);
            m1v[i] = fmaxf(P2 *  CE9, 1e-4f);
            m2v[i] = fmaxf(G  * -CE9, 1e-4f);
            const float t = fmaf(sab, INV9, 1.000001f);
            m3v[i] = fmaxf(__fdividef(EMH, t), 1e-4f);
        }
        *(float4*)(opA)             = make_float4(m0v[0], m0v[1], m0v[2], m0v[3]);
        *(float4*)(opA + H * W)     = make_float4(m1v[0], m1v[1], m1v[2], m1v[3]);
        *(float4*)(opA + 2 * H * W) = make_float4(m2v[0], m2v[1], m2v[2], m2v[3]);
        *(float4*)(opA + 3 * H * W) = make_float4(m3v[0], m3v[1], m3v[2], m3v[3]);
    }

    // ---- window B (rows sr0+1..sr0+3) ----
    {
        float* opB = opA + W;
        float m0v[4], m1v[4], m2v[4], m3v[4];
        #pragma unroll
        for (int i = 0; i < 4; i++) {
            const float S  = cpB[i] + cpB[i+1] + cpB[i+2];
            const float P2 = cqB[i] + cqB[i+1] + cqB[i+2];
            const float G  = cgB[i] + cgB[i+1] + cgB[i+2];
            const float mean = S * INV9;
            const float ssq  = fmaf(-S, mean, P2);
            float sab = 0.0f;
            #pragma unroll
            for (int r = 1; r < 4; r++) {
                sab += fabsf(p[r][i]     - mean);
                sab += fabsf(p[r][i + 1] - mean);
                sab += fabsf(p[r][i + 2] - mean);
            }
            m0v[i] = fminf(fmaxf(ssq * CCLP, 1e-4f), C89E);
            m1v[i] = fmaxf(P2 *  CE9, 1e-4f);
            m2v[i] = fmaxf(G  * -CE9, 1e-4f);
            const float t = fmaf(sab, INV9, 1.000001f);
            m3v[i] = fmaxf(__fdividef(EMH, t), 1e-4f);
        }
        *(float4*)(opB)             = make_float4(m0v[0], m0v[1], m0v[2], m0v[3]);
        *(float4*)(opB + H * W)     = make_float4(m1v[0], m1v[1], m1v[2], m1v[3]);
        *(float4*)(opB + 2 * H * W) = make_float4(m2v[0], m2v[1], m2v[2], m2v[3]);
        *(float4*)(opB + 3 * H * W) = make_float4(m3v[0], m3v[1], m3v[2], m3v[3]);
    }
}

extern "C" void kernel_launch(void* const* d_in, const int* in_sizes, int n_in,
                              void* d_out, int out_size) {
    const float* x = (const float*)d_in[0];
    float* out = (float*)d_out;
    dim3 block(32, 8);
    dim3 grid(H / TILE_H, NPLANES);   // (8, 512)
    medseg_kernel<<<grid, block>>>(x, out);
}

// round 5
// speedup vs baseline: 1.1169x; 1.1169x over previous
#include <cuda_runtime.h>

// MedSegNet texture features, algebraically folded (theta=1):
//   g        = cl*ln(cl), cl = max(p,1e-6)  (precomputed once per input cell)
//   S,P2,G   = 3x3 box sums of p, p^2, g  via per-thread column sums
//   ssq      = P2 - S*mean   (== sum (p-mean)^2)
//   contrast*e^-.5 = min(max(ssq*67392.295, 1e-4), 8/9*e^-.5)
//   M(f)     = fmaxf(f * exp(-0.5), 1e-4)
// Round 5: Round-3 structure (1x4 px/thread, best so far) + occupancy bump:
// __launch_bounds__(256,7) caps regs at 36 -> 7 blocks/SM (87.5% occ).
// Outputs stored per-feature as soon as ready to shrink live ranges.

#define H 128
#define W 128
#define NPLANES 512        // B*C = 8*64
#define TILE_H 16
#define SH (TILE_H + 2)
#define SW2 132            // padded row stride (16B-aligned rows)
#define GPAD (-1.3815511e-5f)   // 1e-6 * ln(1e-6)

__global__ __launch_bounds__(256, 7)
void medseg_kernel(const float* __restrict__ x, float* __restrict__ out) {
    const int bc = blockIdx.y;                 // plane in [0, 512)
    const int rowBase = blockIdx.x * TILE_H;   // row tile

    __shared__ __align__(16) float sp[SH][SW2];
    __shared__ __align__(16) float sg[SH][SW2];

    const int tx = threadIdx.x;                // 0..31
    const int ty = threadIdx.y;                // 0..7

    const float* __restrict__ plane = x + (size_t)bc * (H * W);

    // ---- load phase: warp ty fills shared rows ty, ty+8, ty+16 ----
    #pragma unroll
    for (int rep = 0; rep < 3; rep++) {
        const int sr = ty + rep * 8;
        if (sr < SH) {
            const int gr = rowBase + sr - 1;
            if ((unsigned)gr < (unsigned)H) {
                const float* __restrict__ rp = plane + gr * W;
                #pragma unroll
                for (int k = 0; k < 4; k++) {
                    const float p = rp[tx + 32 * k];
                    const float cl = fmaxf(p, 1e-6f);
                    sp[sr][tx + 32 * k + 1] = p;
                    sg[sr][tx + 32 * k + 1] = cl * __logf(cl);
                }
            } else {
                #pragma unroll
                for (int k = 0; k < 4; k++) {
                    sp[sr][tx + 32 * k + 1] = 0.0f;
                    sg[sr][tx + 32 * k + 1] = GPAD;
                }
            }
            if (tx == 0) { sp[sr][0]   = 0.0f;  sg[sr][0]   = GPAD; }
            if (tx == 1) { sp[sr][129] = 0.0f;  sg[sr][129] = GPAD; }
        }
    }
    __syncthreads();

    const float INV9 = 1.0f / 9.0f;
    const float EMH  = 0.60653066f;            // exp(-0.5)
    const float C89E = 0.53913838f;            // (8/9)*exp(-0.5)
    const float CCLP = 67392.295f;             // (1e6/9)*exp(-0.5)
    const float CE9  = 0.067392295f;           // exp(-0.5)/9

    float* __restrict__ outp = out + (size_t)(4 * bc) * (H * W);

    #pragma unroll
    for (int rr = 0; rr < 2; rr++) {
        const int lr = ty + rr * 8;            // local output row
        const int sr = lr + 1;
        const int sc = 4 * tx;                 // shared col of (global col 4tx - 1)

        float* op = outp + (rowBase + lr) * W + 4 * tx;

        // 3x6 register block of p (aligned LDS.128 + LDS.64)
        float p[3][6];
        #pragma unroll
        for (int r = 0; r < 3; r++) {
            const float4 a = *(const float4*)&sp[sr - 1 + r][sc];
            const float2 b = *(const float2*)&sp[sr - 1 + r][sc + 4];
            p[r][0]=a.x; p[r][1]=a.y; p[r][2]=a.z; p[r][3]=a.w; p[r][4]=b.x; p[r][5]=b.y;
        }

        // ---- entropy first: g consumed immediately, never co-live with the rest ----
        {
            float cg[6];
            #pragma unroll
            for (int j = 0; j < 6; j++) cg[j] = 0.0f;
            #pragma unroll
            for (int r = 0; r < 3; r++) {
                const float4 c = *(const float4*)&sg[sr - 1 + r][sc];
                const float2 d = *(const float2*)&sg[sr - 1 + r][sc + 4];
                cg[0] += c.x; cg[1] += c.y; cg[2] += c.z;
                cg[3] += c.w; cg[4] += d.x; cg[5] += d.y;
            }
            float4 m2;
            m2.x = fmaxf((cg[0] + cg[1] + cg[2]) * -CE9, 1e-4f);
            m2.y = fmaxf((cg[1] + cg[2] + cg[3]) * -CE9, 1e-4f);
            m2.z = fmaxf((cg[2] + cg[3] + cg[4]) * -CE9, 1e-4f);
            m2.w = fmaxf((cg[3] + cg[4] + cg[5]) * -CE9, 1e-4f);
            *(float4*)(op + 2 * H * W) = m2;
        }

        // ---- p / p^2 column sums ----
        float cp[6], cq[6];
        #pragma unroll
        for (int j = 0; j < 6; j++) {
            cp[j] = p[0][j] + p[1][j] + p[2][j];
            cq[j] = fmaf(p[0][j], p[0][j], fmaf(p[1][j], p[1][j], p[2][j] * p[2][j]));
        }

        // energy
        {
            float4 m1;
            m1.x = fmaxf((cq[0] + cq[1] + cq[2]) * CE9, 1e-4f);
            m1.y = fmaxf((cq[1] + cq[2] + cq[3]) * CE9, 1e-4f);
            m1.z = fmaxf((cq[2] + cq[3] + cq[4]) * CE9, 1e-4f);
            m1.w = fmaxf((cq[3] + cq[4] + cq[5]) * CE9, 1e-4f);
            *(float4*)(op + H * W) = m1;
        }

        // contrast + homogeneity (need mean per pixel)
        float4 m0, m3;
        #pragma unroll
        for (int i = 0; i < 4; i++) {
            const float S  = cp[i] + cp[i+1] + cp[i+2];
            const float P2 = cq[i] + cq[i+1] + cq[i+2];
            const float mean = S * INV9;
            const float ssq  = fmaf(-S, mean, P2);      // sum (p-mean)^2

            float sab = 0.0f;                            // sum |p-mean|
            #pragma unroll
            for (int r = 0; r < 3; r++) {
                sab += fabsf(p[r][i]     - mean);
                sab += fabsf(p[r][i + 1] - mean);
                sab += fabsf(p[r][i + 2] - mean);
            }

            const float mc = fminf(fmaxf(ssq * CCLP, 1e-4f), C89E);
            const float t  = fmaf(sab, INV9, 1.000001f);
            const float mh = fmaxf(__fdividef(EMH, t), 1e-4f);
            if (i == 0) { m0.x = mc; m3.x = mh; }
            if (i == 1) { m0.y = mc; m3.y = mh; }
            if (i == 2) { m0.z = mc; m3.z = mh; }
            if (i == 3) { m0.w = mc; m3.w = mh; }
        }
        *(float4*)(op)             = m0;
        *(float4*)(op + 3 * H * W) = m3;
    }
}

extern "C" void kernel_launch(void* const* d_in, const int* in_sizes, int n_in,
                              void* d_out, int out_size) {
    const float* x = (const float*)d_in[0];
    float* out = (float*)d_out;
    dim3 block(32, 8);
    dim3 grid(H / TILE_H, NPLANES);   // (8, 512)
    medseg_kernel<<<grid, block>>>(x, out);
}

// round 6
// speedup vs baseline: 1.1250x; 1.0072x over previous
#include <cuda_runtime.h>

// MedSegNet texture features, algebraically folded (theta=1):
//   g   = cl*ln(cl), cl = max(p,1e-6)   (once per input cell, in load phase)
//   3x3 box sums of p, p^2, g via PACKED f32x2 vertical column sums
//   ssq = P2 - S*mean; contrast*e^-.5 = min(max(ssq*67392.295,1e-4), 8/9*e^-.5)
//   M(f) = fmaxf(f*exp(-0.5), 1e-4)
// Round 6: f32x2 (FFMA2/FADD2) packed column sums -- pairs come pre-aligned
// from LDS.128/LDS.64, so packing is free; unpack is mov.b64 (coalescible).

#define H 128
#define W 128
#define NPLANES 512        // B*C = 8*64
#define TILE_H 16
#define SH (TILE_H + 2)
#define SW2 132            // padded row stride (16B-aligned rows)
#define GPAD (-1.3815511e-5f)   // 1e-6 * ln(1e-6)

typedef unsigned long long u64;

__device__ __forceinline__ u64 add2(u64 a, u64 b) {
    u64 d; asm("add.rn.f32x2 %0,%1,%2;" : "=l"(d) : "l"(a), "l"(b)); return d;
}
__device__ __forceinline__ u64 mul2(u64 a, u64 b) {
    u64 d; asm("mul.rn.f32x2 %0,%1,%2;" : "=l"(d) : "l"(a), "l"(b)); return d;
}
__device__ __forceinline__ u64 fma2(u64 a, u64 b, u64 c) {
    u64 d; asm("fma.rn.f32x2 %0,%1,%2,%3;" : "=l"(d) : "l"(a), "l"(b), "l"(c)); return d;
}
__device__ __forceinline__ float2 unpk(u64 v) {
    float2 r; asm("mov.b64 {%0,%1},%2;" : "=f"(r.x), "=f"(r.y) : "l"(v)); return r;
}

__global__ __launch_bounds__(256)
void medseg_kernel(const float* __restrict__ x, float* __restrict__ out) {
    const int bc = blockIdx.y;
    const int rowBase = blockIdx.x * TILE_H;

    __shared__ __align__(16) float sp[SH][SW2];
    __shared__ __align__(16) float sg[SH][SW2];

    const int tx = threadIdx.x;                // 0..31
    const int ty = threadIdx.y;                // 0..7

    const float* __restrict__ plane = x + (size_t)bc * (H * W);

    // ---- load phase: warp ty fills shared rows ty, ty+8, ty+16 ----
    #pragma unroll
    for (int rep = 0; rep < 3; rep++) {
        const int sr = ty + rep * 8;
        if (sr < SH) {
            const int gr = rowBase + sr - 1;
            if ((unsigned)gr < (unsigned)H) {
                const float* __restrict__ rp = plane + gr * W;
                #pragma unroll
                for (int k = 0; k < 4; k++) {
                    const float p = rp[tx + 32 * k];
                    const float cl = fmaxf(p, 1e-6f);
                    sp[sr][tx + 32 * k + 1] = p;
                    sg[sr][tx + 32 * k + 1] = cl * __logf(cl);
                }
            } else {
                #pragma unroll
                for (int k = 0; k < 4; k++) {
                    sp[sr][tx + 32 * k + 1] = 0.0f;
                    sg[sr][tx + 32 * k + 1] = GPAD;
                }
            }
            if (tx == 0) { sp[sr][0]   = 0.0f;  sg[sr][0]   = GPAD; }
            if (tx == 1) { sp[sr][129] = 0.0f;  sg[sr][129] = GPAD; }
        }
    }
    __syncthreads();

    const float INV9 = 1.0f / 9.0f;
    const float EMH  = 0.60653066f;            // exp(-0.5)
    const float C89E = 0.53913838f;            // (8/9)*exp(-0.5)
    const float CCLP = 67392.295f;             // (1e6/9)*exp(-0.5)
    const float CE9  = 0.067392295f;           // exp(-0.5)/9

    float* __restrict__ outp = out + (size_t)(4 * bc) * (H * W);

    #pragma unroll
    for (int rr = 0; rr < 2; rr++) {
        const int lr = ty + rr * 8;            // local output row
        const int sr = lr + 1;
        const int sc = 4 * tx;                 // shared col of (global col 4tx - 1)
        float* op = outp + (rowBase + lr) * W + 4 * tx;

        // ---- entropy: packed g column sums, consumed immediately ----
        {
            const ulonglong2 Ga0 = *(const ulonglong2*)&sg[sr - 1][sc];
            const u64        Gb0 = *(const u64*)&sg[sr - 1][sc + 4];
            const ulonglong2 Ga1 = *(const ulonglong2*)&sg[sr    ][sc];
            const u64        Gb1 = *(const u64*)&sg[sr    ][sc + 4];
            const ulonglong2 Ga2 = *(const ulonglong2*)&sg[sr + 1][sc];
            const u64        Gb2 = *(const u64*)&sg[sr + 1][sc + 4];

            const float2 cg01 = unpk(add2(add2(Ga0.x, Ga1.x), Ga2.x));
            const float2 cg23 = unpk(add2(add2(Ga0.y, Ga1.y), Ga2.y));
            const float2 cg45 = unpk(add2(add2(Gb0,   Gb1),   Gb2));

            float4 m2;
            m2.x = fmaxf((cg01.x + cg01.y + cg23.x) * -CE9, 1e-4f);
            m2.y = fmaxf((cg01.y + cg23.x + cg23.y) * -CE9, 1e-4f);
            m2.z = fmaxf((cg23.x + cg23.y + cg45.x) * -CE9, 1e-4f);
            m2.w = fmaxf((cg23.y + cg45.x + cg45.y) * -CE9, 1e-4f);
            *(float4*)(op + 2 * H * W) = m2;
        }

        // ---- p rows (packed) ----
        const ulonglong2 Pa0 = *(const ulonglong2*)&sp[sr - 1][sc];
        const u64        Pb0 = *(const u64*)&sp[sr - 1][sc + 4];
        const ulonglong2 Pa1 = *(const ulonglong2*)&sp[sr    ][sc];
        const u64        Pb1 = *(const u64*)&sp[sr    ][sc + 4];
        const ulonglong2 Pa2 = *(const ulonglong2*)&sp[sr + 1][sc];
        const u64        Pb2 = *(const u64*)&sp[sr + 1][sc + 4];

        // packed vertical column sums of p and p^2
        const float2 cp01 = unpk(add2(add2(Pa0.x, Pa1.x), Pa2.x));
        const float2 cp23 = unpk(add2(add2(Pa0.y, Pa1.y), Pa2.y));
        const float2 cp45 = unpk(add2(add2(Pb0,   Pb1),   Pb2));
        const float2 cq01 = unpk(fma2(Pa0.x, Pa0.x, fma2(Pa1.x, Pa1.x, mul2(Pa2.x, Pa2.x))));
        const float2 cq23 = unpk(fma2(Pa0.y, Pa0.y, fma2(Pa1.y, Pa1.y, mul2(Pa2.y, Pa2.y))));
        const float2 cq45 = unpk(fma2(Pb0,   Pb0,   fma2(Pb1,   Pb1,   mul2(Pb2,   Pb2))));

        const float cp[6] = {cp01.x, cp01.y, cp23.x, cp23.y, cp45.x, cp45.y};
        const float cq[6] = {cq01.x, cq01.y, cq23.x, cq23.y, cq45.x, cq45.y};

        // energy
        float P2v[4];
        {
            float4 m1;
            P2v[0] = cq[0] + cq[1] + cq[2];  m1.x = fmaxf(P2v[0] * CE9, 1e-4f);
            P2v[1] = cq[1] + cq[2] + cq[3];  m1.y = fmaxf(P2v[1] * CE9, 1e-4f);
            P2v[2] = cq[2] + cq[3] + cq[4];  m1.z = fmaxf(P2v[2] * CE9, 1e-4f);
            P2v[3] = cq[3] + cq[4] + cq[5];  m1.w = fmaxf(P2v[3] * CE9, 1e-4f);
            *(float4*)(op + H * W) = m1;
        }

        // scalar p for the non-separable sab pass (unpack = mov.b64, coalescible)
        float p[3][6];
        {
            float2 t;
            t = unpk(Pa0.x); p[0][0]=t.x; p[0][1]=t.y;
            t = unpk(Pa0.y); p[0][2]=t.x; p[0][3]=t.y;
            t = unpk(Pb0);   p[0][4]=t.x; p[0][5]=t.y;
            t = unpk(Pa1.x); p[1][0]=t.x; p[1][1]=t.y;
            t = unpk(Pa1.y); p[1][2]=t.x; p[1][3]=t.y;
            t = unpk(Pb1);   p[1][4]=t.x; p[1][5]=t.y;
            t = unpk(Pa2.x); p[2][0]=t.x; p[2][1]=t.y;
            t = unpk(Pa2.y); p[2][2]=t.x; p[2][3]=t.y;
            t = unpk(Pb2);   p[2][4]=t.x; p[2][5]=t.y;
        }

        // contrast + homogeneity
        float4 m0, m3;
        float mcv[4], mhv[4];
        #pragma unroll
        for (int i = 0; i < 4; i++) {
            const float S    = cp[i] + cp[i+1] + cp[i+2];
            const float mean = S * INV9;
            const float ssq  = fmaf(-S, mean, P2v[i]);   // sum (p-mean)^2

            float sab = 0.0f;                             // sum |p-mean|
            #pragma unroll
            for (int r = 0; r < 3; r++) {
                sab += fabsf(p[r][i]     - mean);
                sab += fabsf(p[r][i + 1] - mean);
                sab += fabsf(p[r][i + 2] - mean);
            }

            mcv[i] = fminf(fmaxf(ssq * CCLP, 1e-4f), C89E);
            const float t = fmaf(sab, INV9, 1.000001f);
            mhv[i] = fmaxf(__fdividef(EMH, t), 1e-4f);
        }
        m0 = make_float4(mcv[0], mcv[1], mcv[2], mcv[3]);
        m3 = make_float4(mhv[0], mhv[1], mhv[2], mhv[3]);
        *(float4*)(op)             = m0;
        *(float4*)(op + 3 * H * W) = m3;
    }
}

extern "C" void kernel_launch(void* const* d_in, const int* in_sizes, int n_in,
                              void* d_out, int out_size) {
    const float* x = (const float*)d_in[0];
    float* out = (float*)d_out;
    dim3 block(32, 8);
    dim3 grid(H / TILE_H, NPLANES);   // (8, 512)
    medseg_kernel<<<grid, block>>>(x, out);
}